// round 12
// baseline (speedup 1.0000x reference)
#include <cuda_runtime.h>

#define BB 2
#define CIN 256
#define OCH 256
#define HH 48
#define WW 48
#define HP 54
#define WP 54
#define NPOS (HP*WP)      // 2916
#define NP2 (BB*NPOS)     // 5832
#define KS 7
#define KK 49
#define ND2 85            // symmetric offsets: dr=0,dc>=0 (7) + dr in [1,6] x dc in [-6,6] (78)

// Scratch (device globals: no allocation allowed)
__device__ float g_QK[BB*NPOS*OCH];      // [b][p][o]   ~6.0 MB
__device__ float g_V [BB*NPOS*OCH];      // [b][p][o]   ~6.0 MB
__device__ float g_CORR[ND2*NP2];        // [d][b*NPOS+p]  ~2.0 MB  (offset-major)
__device__ float g_AB[BB*NPOS*16];       // [b][p][0..6]=A(rel_h), [8..14]=B(rel_w)

// Compile-time (block-independent) corr-offset table: di*NP2 + r*54 + c
struct CorrTab { unsigned int v[2401]; };
static constexpr CorrTab make_tab() {
    CorrTab t{};
    for (int e = 0; e < 2401; e++) {
        int ii = e / 49, jj = e % 49;
        int ir = ii / 7, ic = ii % 7, jr = jj / 7, jc = jj % 7;
        int dr = jr - ir, dc = jc - ic;
        int r = 0, c = 0;
        if (dr > 0 || (dr == 0 && dc >= 0)) { r = ir; c = ic; }
        else { r = jr; c = jc; dr = -dr; dc = -dc; }
        int di = (dr == 0) ? dc : (7 + (dr - 1)*13 + dc + 6);
        t.v[e] = (unsigned int)(di*NP2 + r*54 + c);
    }
    return t;
}
__constant__ CorrTab c_tab = make_tab();

// packed f32x2 FMA (Blackwell)
__device__ __forceinline__ void ffma2(unsigned long long &d, unsigned long long a, unsigned long long b) {
    asm("fma.rn.f32x2 %0, %1, %2, %0;" : "+l"(d) : "l"(a), "l"(b));
}
__device__ __forceinline__ float2 u2f(unsigned long long u) {
    float2 f; asm("mov.b64 {%0,%1}, %2;" : "=f"(f.x), "=f"(f.y) : "l"(u)); return f;
}
__device__ __forceinline__ unsigned long long dup2(float a) {
    unsigned long long r; asm("mov.b64 %0, {%1, %1};" : "=l"(r) : "f"(a)); return r;
}
// 4-byte async copy global->shared (LDGSTS): no result register, high MLP.
__device__ __forceinline__ void cpa4(unsigned int saddr, const float* g) {
    asm volatile("cp.async.ca.shared.global [%0], [%1], 4;" :: "r"(saddr), "l"(g));
}
__device__ __forceinline__ void cpa_commit_wait() {
    asm volatile("cp.async.commit_group;\ncp.async.wait_group 0;" ::: "memory");
}

// ---------------------------------------------------------------------------
// Kernel 1: fused {border-zero + 1x1 conv GEMM}.
__global__ void __launch_bounds__(256) kGemmZ(const float* __restrict__ x,
                                              const float* __restrict__ wk,
                                              const float* __restrict__ wv) {
    if (blockIdx.y == 4) {       // border zeroing
        float4 z = make_float4(0.f, 0.f, 0.f, 0.f);
        for (int idx = blockIdx.x*256 + threadIdx.x; idx < 156672; idx += 9216) {
            int c4  = idx & 63;
            int t   = idx >> 6;
            int bp  = t % 612;
            int t2  = t / 612;
            int b   = t2 & 1;
            int arr = t2 >> 1;
            int row, col;
            if (bp < 324) { int r = bp / 54; row = (r < 3) ? r : r + 48; col = bp % 54; }
            else { int u = bp - 324; row = 3 + u / 6; int c6 = u % 6; col = (c6 < 3) ? c6 : c6 + 48; }
            long off = ((long)(b*NPOS + row*54 + col)*256) + c4*4;
            if (arr == 0) *(float4*)&g_QK[off] = z;
            else          *(float4*)&g_V [off] = z;
        }
        return;
    }
    __shared__ float As[16][132];
    __shared__ float Bs[16][132];
    int tid = threadIdx.x;
    int n0 = blockIdx.x * 128;
    int m0 = blockIdx.y * 128;
    int tx = tid & 15, ty = tid >> 4;
    unsigned long long acc[8][4];
    #pragma unroll
    for (int i = 0; i < 8; i++)
        #pragma unroll
        for (int j = 0; j < 4; j++) acc[i][j] = 0ull;

    for (int kt = 0; kt < 256; kt += 16) {
        #pragma unroll
        for (int i = 0; i < 8; i++) {
            int flat = i*256 + tid;
            int k = flat >> 7, n = flat & 127;
            int nn = n0 + n;
            int b = nn / 2304, s = nn % 2304;
            As[k][n] = x[(b*256 + kt + k)*2304 + s];
        }
        #pragma unroll
        for (int i = 0; i < 8; i++) {
            int flat = i*256 + tid;
            int k = flat & 15, m = flat >> 4;
            int mm = m0 + m;
            Bs[k][m] = (mm < 256) ? wk[mm*256 + kt + k] : wv[(mm-256)*256 + kt + k];
        }
        __syncthreads();
        #pragma unroll
        for (int k = 0; k < 16; k++) {
            float4 a03 = *(const float4*)&As[k][4*ty];
            float4 a47 = *(const float4*)&As[k][64 + 4*ty];
            ulonglong2 b03 = *(const ulonglong2*)&Bs[k][4*tx];
            ulonglong2 b47 = *(const ulonglong2*)&Bs[k][64 + 4*tx];
            unsigned long long A[8] = {dup2(a03.x), dup2(a03.y), dup2(a03.z), dup2(a03.w),
                                       dup2(a47.x), dup2(a47.y), dup2(a47.z), dup2(a47.w)};
            unsigned long long B[4] = {b03.x, b03.y, b47.x, b47.y};
            #pragma unroll
            for (int i = 0; i < 8; i++)
                #pragma unroll
                for (int j = 0; j < 4; j++)
                    ffma2(acc[i][j], A[i], B[j]);
        }
        __syncthreads();
    }
    #pragma unroll
    for (int i = 0; i < 8; i++) {
        int n = n0 + ((i < 4) ? (ty*4 + i) : (64 + ty*4 + i - 4));
        int b = n / 2304, rem = n % 2304;
        int h = rem / 48, w = rem % 48;
        int pidx = (h + 3)*54 + (w + 3);
        long rowq = (long)(b*NPOS + pidx)*256;
        float2 p0 = u2f(acc[i][0]), p1 = u2f(acc[i][1]);
        float2 p2 = u2f(acc[i][2]), p3 = u2f(acc[i][3]);
        float4 va = make_float4(p0.x, p0.y, p1.x, p1.y);
        float4 vb = make_float4(p2.x, p2.y, p3.x, p3.y);
        int ma = m0 + tx*4;
        int mb = m0 + 64 + tx*4;
        if (ma < 256) *(float4*)&g_QK[rowq + ma]        = va;
        else          *(float4*)&g_V [rowq + (ma-256)]  = va;
        if (mb < 256) *(float4*)&g_QK[rowq + mb]        = vb;
        else          *(float4*)&g_V [rowq + (mb-256)]  = vb;
    }
}

// ---------------------------------------------------------------------------
// Kernel 2: CORR[d][b,p] = sum_c QK[b,p,c]*QK[b,p+d,c] for 85 symmetric offsets.
__global__ void kCorr() {
    __shared__ float4 sQ4[10*20*9];
    int b  = blockIdx.z;
    int r0 = blockIdx.y * 4;
    int c0 = blockIdx.x * 8;
    int tid = threadIdx.x;
    int pl = tid & 31;
    int wg = tid >> 5;
    int pr = pl >> 3, pc = pl & 7;
    int dbase = wg * 11;

    int doff[11];
    #pragma unroll
    for (int k = 0; k < 11; k++) {
        int t = dbase + k; if (t > 84) t = 84;
        int dr, dc;
        if (t < 7) { dr = 0; dc = t; }
        else { int u = t - 7; dr = u/13 + 1; dc = u%13 - 6; }
        doff[k] = (dr*20 + dc) * 9;
    }
    float acc[11];
    #pragma unroll
    for (int k = 0; k < 11; k++) acc[k] = 0.f;

    int own4 = (pr*20 + (pc + 6)) * 9;

    for (int cc = 0; cc < 256; cc += 32) {
        #pragma unroll
        for (int it = 0; it < 7; it++) {
            int flat = it*256 + tid;
            if (flat < 1600) {
                int pos = flat >> 3, c4 = flat & 7;
                int hr = pos / 20, hc = pos % 20;
                int gr = r0 + hr, gc = c0 - 6 + hc;
                float4 v = make_float4(0.f, 0.f, 0.f, 0.f);
                if (gr < 54 && gc >= 0 && gc < 54)
                    v = *(const float4*)&g_QK[(long)((b*NPOS + gr*54 + gc))*256 + cc + c4*4];
                sQ4[pos*9 + c4] = v;
            }
        }
        __syncthreads();
        #pragma unroll
        for (int c4 = 0; c4 < 8; c4++) {
            float4 q = sQ4[own4 + c4];
            #pragma unroll
            for (int k = 0; k < 11; k++) {
                float4 v = sQ4[own4 + doff[k] + c4];
                acc[k] += q.x*v.x + q.y*v.y + q.z*v.z + q.w*v.w;
            }
        }
        __syncthreads();
    }
    int gr = r0 + pr, gc = c0 + pc;
    if (gr < 54 && gc < 54) {
        int pg = b*NPOS + gr*54 + gc;
        #pragma unroll
        for (int k = 0; k < 11; k++) {
            int t = dbase + k;
            if (t < 85) g_CORR[t*NP2 + pg] = acc[k];
        }
    }
}

// ---------------------------------------------------------------------------
// Kernel 3: bias projections, warp-per-position, float4 coalesced.
__global__ void __launch_bounds__(256) kAB(const float* __restrict__ relh,
                                           const float* __restrict__ relw) {
    __shared__ float sR[2][7][128];
    int tid = threadIdx.x;
    for (int i = tid; i < 1792; i += 256) {
        int half = i / 896, j = i % 896;
        int r = j / 128, o = j % 128;
        sR[half][r][o] = (half == 0) ? relh[o*7 + r] : relw[o*7 + r];
    }
    __syncthreads();

    int lane = tid & 31, wid = tid >> 5;
    int p = blockIdx.x * 8 + wid;
    const float* qrow = &g_QK[(long)p*256];
    float4 q1 = *(const float4*)&qrow[4*lane];
    float4 q2 = *(const float4*)&qrow[128 + 4*lane];

    #pragma unroll
    for (int r = 0; r < 7; r++) {
        float4 rh = *(const float4*)&sR[0][r][4*lane];
        float4 rw = *(const float4*)&sR[1][r][4*lane];
        float sh = rh.x*q1.x + rh.y*q1.y + rh.z*q1.z + rh.w*q1.w;
        float sw = rw.x*q2.x + rw.y*q2.y + rw.z*q2.z + rw.w*q2.w;
        #pragma unroll
        for (int o = 16; o; o >>= 1) {
            sh += __shfl_xor_sync(0xffffffffu, sh, o);
            sw += __shfl_xor_sync(0xffffffffu, sw, o);
        }
        if (lane == 0) {
            g_AB[(long)p*16 + r]     = sh;
            g_AB[(long)p*16 + 8 + r] = sw;
        }
    }
}

// ---------------------------------------------------------------------------
// Kernel 4: 8-px row strip (grid 576 -> ~4 blocks/SM). cp.async B1 with
// compile-time constant offset table; warp-per-pixel softmax; 28.4 KB smem.
// Layout (float units):
//   S_ABT = 0    : 16 x 98  bias projections [e][r*14+c]     (6.3 KB)
//   S_S   = 1568 : 343 x 9  raw corr chunk                   (12.3 KB)
//   S_WV  = 6664 : 49 x 9   avg weights                      (1.8 KB)
//   Phase C: sV (98 x 68 = 6664 floats, 16B-aligned stride) overlays
//   [0..6664) — sWv at 6664 survives.
#define S_ABT 0
#define S_S   1568
#define S_WV  6664
#define SMEM_FLOATS 7105    // 28420 bytes (static)

__global__ void __launch_bounds__(256) kAttn(float* __restrict__ out) {
    __shared__ __align__(16) float smem[SMEM_FLOATS];
    float* sABt = smem + S_ABT;
    float* sS   = smem + S_S;
    float* sWv  = smem + S_WV;
    float* sV   = smem;              // phase-C overlay

    int tid = threadIdx.x;
    int w0 = blockIdx.x * 8;
    int h  = blockIdx.y;
    int b  = blockIdx.z;
    int bbase = b*NPOS;
    int blkbase = bbase + h*54 + w0;

    // Stage bias projections [e][pos], stride 98 (1568 = 6*256 + 32)
    #pragma unroll
    for (int it = 0; it < 7; it++) {
        int i = it*256 + tid;
        if (i < 1568) {
            int e = i & 15, p2 = i >> 4;
            int r = p2 / 14, cpos = p2 % 14;
            sABt[e*98 + p2] = g_AB[(long)(bbase + (h+r)*54 + w0 + cpos)*16 + e];
        }
    }
    __syncthreads();

    float wacc0 = 0.f, wacc1 = 0.f;
    int lane = tid & 31, px_b = tid >> 5;     // B2: warp px_b, lane = column
    int pxc  = tid & 7,  qid  = tid >> 3;     // B1: 8 px lanes, 32 q slots
    const float* pC = g_CORR + blkbase + pxc;
    int l32 = lane + 32;
    bool has1 = lane < 17;
    int jm0 = (lane/7)*14 + lane%7;
    int jm1 = (l32/7)*14 + l32%7;

    for (int chk = 0; chk < 7; chk++) {
        int ebase = chk*343;
        // B1: async-copy 343 x 8 raw corr values (343 = 10*32 + 23)
        #pragma unroll
        for (int it = 0; it < 10; it++) {
            int q = it*32 + qid;
            unsigned int t = c_tab.v[ebase + q];
            unsigned int saddr = (unsigned int)__cvta_generic_to_shared(&sS[q*9 + pxc]);
            cpa4(saddr, pC + t);
        }
        if (qid < 23) {
            int q = 320 + qid;
            unsigned int t = c_tab.v[ebase + q];
            unsigned int saddr = (unsigned int)__cvta_generic_to_shared(&sS[q*9 + pxc]);
            cpa4(saddr, pC + t);
        }
        cpa_commit_wait();
        __syncthreads();
        // B2: bias add + full-warp softmax per row; accumulate column sums
        float a0 = sABt[chk*98 + jm0 + px_b];
        float a1 = has1 ? sABt[chk*98 + jm1 + px_b] : 0.f;
        #pragma unroll
        for (int rr = 0; rr < 7; rr++) {
            const float* pBr = sABt + (8+rr)*98 + px_b;
            float v0 = sS[(rr*49 + lane)*9 + px_b] + a0 + pBr[jm0];
            float v1 = has1 ? (sS[(rr*49 + l32)*9 + px_b] + a1 + pBr[jm1]) : -1e30f;
            float m = fmaxf(v0, v1);
            #pragma unroll
            for (int o = 16; o; o >>= 1) m = fmaxf(m, __shfl_xor_sync(0xffffffffu, m, o));
            float e0 = __expf(v0 - m);
            float e1 = has1 ? __expf(v1 - m) : 0.f;
            float s = e0 + e1;
            #pragma unroll
            for (int o = 16; o; o >>= 1) s += __shfl_xor_sync(0xffffffffu, s, o);
            float inv = 1.f / s;
            wacc0 += e0*inv; wacc1 += e1*inv;
        }
        __syncthreads();
    }
    sWv[lane*9 + px_b] = wacc0 * (1.f/49.f);
    if (has1) sWv[l32*9 + px_b] = wacc1 * (1.f/49.f);
    __syncthreads();

    // Phase C: V gather via smem staging, 64-channel chunks, float2/thread
    int px = tid & 7, tc = tid >> 3;        // tc in [0,32): channel pair
    for (int cc = 0; cc < 256; cc += 64) {
        #pragma unroll
        for (int it = 0; it < 7; it++) {
            int i = it*256 + tid;
            if (i < 1568) {
                int f4 = i & 15, p2 = i >> 4;
                int r = p2 / 14, cpos = p2 % 14;
                *(float4*)&sV[p2*68 + f4*4] =
                    *(const float4*)&g_V[(long)(bbase + (h+r)*54 + w0 + cpos)*256 + cc + f4*4];
            }
        }
        __syncthreads();
        float2 acc = make_float2(0.f, 0.f);
        #pragma unroll
        for (int jj = 0; jj < 49; jj++) {
            int jpos = (jj/7)*14 + (jj%7);
            float w = sWv[jj*9 + px];
            float2 v = *(const float2*)&sV[(jpos + px)*68 + tc*2];
            acc.x += w*v.x; acc.y += w*v.y;
        }
        int c = cc + tc*2;
        int ob = ((b*256 + c)*48 + h)*48 + w0 + px;
        out[ob]        = acc.x;
        out[ob + 2304] = acc.y;
        __syncthreads();
    }
}

// ---------------------------------------------------------------------------
extern "C" void kernel_launch(void* const* d_in, const int* in_sizes, int n_in,
                              void* d_out, int out_size) {
    const float* x    = (const float*)d_in[0];
    const float* wk   = (const float*)d_in[1];
    const float* wv   = (const float*)d_in[2];
    const float* relh = (const float*)d_in[3];
    const float* relw = (const float*)d_in[4];
    float* out = (float*)d_out;

    kGemmZ<<<dim3(36, 5), 256>>>(x, wk, wv);
    kCorr<<<dim3(7, 14, 2), 256>>>();
    kAB<<<729, 256>>>(relh, relw);
    kAttn<<<dim3(6, 48, 2), 256>>>(out);
}

// round 13
// speedup vs baseline: 1.0181x; 1.0181x over previous
#include <cuda_runtime.h>

#define BB 2
#define CIN 256
#define OCH 256
#define HH 48
#define WW 48
#define HP 54
#define WP 54
#define NPOS (HP*WP)      // 2916
#define NP2 (BB*NPOS)     // 5832
#define KS 7
#define KK 49
#define ND2 85            // symmetric offsets: dr=0,dc>=0 (7) + dr in [1,6] x dc in [-6,6] (78)

// Scratch (device globals: no allocation allowed)
__device__ float g_QK[BB*NPOS*OCH];      // [b][p][o]   ~6.0 MB
__device__ float g_V [BB*NPOS*OCH];      // [b][p][o]   ~6.0 MB
__device__ float g_CORR[ND2*NP2];        // [d][b*NPOS+p]  ~2.0 MB  (offset-major)
__device__ float g_AB[BB*NPOS*16];       // [b][p][0..6]=A(rel_h), [8..14]=B(rel_w)

// Compile-time (block-independent) corr-offset table: di*NP2 + r*54 + c
struct CorrTab { unsigned int v[2401]; };
static constexpr CorrTab make_tab() {
    CorrTab t{};
    for (int e = 0; e < 2401; e++) {
        int ii = e / 49, jj = e % 49;
        int ir = ii / 7, ic = ii % 7, jr = jj / 7, jc = jj % 7;
        int dr = jr - ir, dc = jc - ic;
        int r = 0, c = 0;
        if (dr > 0 || (dr == 0 && dc >= 0)) { r = ir; c = ic; }
        else { r = jr; c = jc; dr = -dr; dc = -dc; }
        int di = (dr == 0) ? dc : (7 + (dr - 1)*13 + dc + 6);
        t.v[e] = (unsigned int)(di*NP2 + r*54 + c);
    }
    return t;
}
__constant__ CorrTab c_tab = make_tab();

// packed f32x2 FMA (Blackwell)
__device__ __forceinline__ void ffma2(unsigned long long &d, unsigned long long a, unsigned long long b) {
    asm("fma.rn.f32x2 %0, %1, %2, %0;" : "+l"(d) : "l"(a), "l"(b));
}
__device__ __forceinline__ float2 u2f(unsigned long long u) {
    float2 f; asm("mov.b64 {%0,%1}, %2;" : "=f"(f.x), "=f"(f.y) : "l"(u)); return f;
}
__device__ __forceinline__ unsigned long long dup2(float a) {
    unsigned long long r; asm("mov.b64 %0, {%1, %1};" : "=l"(r) : "f"(a)); return r;
}
// 4-byte async copy global->shared (LDGSTS): no result register, high MLP.
__device__ __forceinline__ void cpa4(unsigned int saddr, const float* g) {
    asm volatile("cp.async.ca.shared.global [%0], [%1], 4;" :: "r"(saddr), "l"(g));
}

// ---------------------------------------------------------------------------
// Kernel 1: fused {border-zero + 1x1 conv GEMM}.
__global__ void __launch_bounds__(256) kGemmZ(const float* __restrict__ x,
                                              const float* __restrict__ wk,
                                              const float* __restrict__ wv) {
    if (blockIdx.y == 4) {       // border zeroing
        float4 z = make_float4(0.f, 0.f, 0.f, 0.f);
        for (int idx = blockIdx.x*256 + threadIdx.x; idx < 156672; idx += 9216) {
            int c4  = idx & 63;
            int t   = idx >> 6;
            int bp  = t % 612;
            int t2  = t / 612;
            int b   = t2 & 1;
            int arr = t2 >> 1;
            int row, col;
            if (bp < 324) { int r = bp / 54; row = (r < 3) ? r : r + 48; col = bp % 54; }
            else { int u = bp - 324; row = 3 + u / 6; int c6 = u % 6; col = (c6 < 3) ? c6 : c6 + 48; }
            long off = ((long)(b*NPOS + row*54 + col)*256) + c4*4;
            if (arr == 0) *(float4*)&g_QK[off] = z;
            else          *(float4*)&g_V [off] = z;
        }
        return;
    }
    __shared__ float As[16][132];
    __shared__ float Bs[16][132];
    int tid = threadIdx.x;
    int n0 = blockIdx.x * 128;
    int m0 = blockIdx.y * 128;
    int tx = tid & 15, ty = tid >> 4;
    unsigned long long acc[8][4];
    #pragma unroll
    for (int i = 0; i < 8; i++)
        #pragma unroll
        for (int j = 0; j < 4; j++) acc[i][j] = 0ull;

    for (int kt = 0; kt < 256; kt += 16) {
        #pragma unroll
        for (int i = 0; i < 8; i++) {
            int flat = i*256 + tid;
            int k = flat >> 7, n = flat & 127;
            int nn = n0 + n;
            int b = nn / 2304, s = nn % 2304;
            As[k][n] = x[(b*256 + kt + k)*2304 + s];
        }
        #pragma unroll
        for (int i = 0; i < 8; i++) {
            int flat = i*256 + tid;
            int k = flat & 15, m = flat >> 4;
            int mm = m0 + m;
            Bs[k][m] = (mm < 256) ? wk[mm*256 + kt + k] : wv[(mm-256)*256 + kt + k];
        }
        __syncthreads();
        #pragma unroll
        for (int k = 0; k < 16; k++) {
            float4 a03 = *(const float4*)&As[k][4*ty];
            float4 a47 = *(const float4*)&As[k][64 + 4*ty];
            ulonglong2 b03 = *(const ulonglong2*)&Bs[k][4*tx];
            ulonglong2 b47 = *(const ulonglong2*)&Bs[k][64 + 4*tx];
            unsigned long long A[8] = {dup2(a03.x), dup2(a03.y), dup2(a03.z), dup2(a03.w),
                                       dup2(a47.x), dup2(a47.y), dup2(a47.z), dup2(a47.w)};
            unsigned long long B[4] = {b03.x, b03.y, b47.x, b47.y};
            #pragma unroll
            for (int i = 0; i < 8; i++)
                #pragma unroll
                for (int j = 0; j < 4; j++)
                    ffma2(acc[i][j], A[i], B[j]);
        }
        __syncthreads();
    }
    #pragma unroll
    for (int i = 0; i < 8; i++) {
        int n = n0 + ((i < 4) ? (ty*4 + i) : (64 + ty*4 + i - 4));
        int b = n / 2304, rem = n % 2304;
        int h = rem / 48, w = rem % 48;
        int pidx = (h + 3)*54 + (w + 3);
        long rowq = (long)(b*NPOS + pidx)*256;
        float2 p0 = u2f(acc[i][0]), p1 = u2f(acc[i][1]);
        float2 p2 = u2f(acc[i][2]), p3 = u2f(acc[i][3]);
        float4 va = make_float4(p0.x, p0.y, p1.x, p1.y);
        float4 vb = make_float4(p2.x, p2.y, p3.x, p3.y);
        int ma = m0 + tx*4;
        int mb = m0 + 64 + tx*4;
        if (ma < 256) *(float4*)&g_QK[rowq + ma]        = va;
        else          *(float4*)&g_V [rowq + (ma-256)]  = va;
        if (mb < 256) *(float4*)&g_QK[rowq + mb]        = vb;
        else          *(float4*)&g_V [rowq + (mb-256)]  = vb;
    }
}

// ---------------------------------------------------------------------------
// Kernel 2: CORR[d][b,p] = sum_c QK[b,p,c]*QK[b,p+d,c] for 85 symmetric offsets.
__global__ void kCorr() {
    __shared__ float4 sQ4[10*20*9];
    int b  = blockIdx.z;
    int r0 = blockIdx.y * 4;
    int c0 = blockIdx.x * 8;
    int tid = threadIdx.x;
    int pl = tid & 31;
    int wg = tid >> 5;
    int pr = pl >> 3, pc = pl & 7;
    int dbase = wg * 11;

    int doff[11];
    #pragma unroll
    for (int k = 0; k < 11; k++) {
        int t = dbase + k; if (t > 84) t = 84;
        int dr, dc;
        if (t < 7) { dr = 0; dc = t; }
        else { int u = t - 7; dr = u/13 + 1; dc = u%13 - 6; }
        doff[k] = (dr*20 + dc) * 9;
    }
    float acc[11];
    #pragma unroll
    for (int k = 0; k < 11; k++) acc[k] = 0.f;

    int own4 = (pr*20 + (pc + 6)) * 9;

    for (int cc = 0; cc < 256; cc += 32) {
        #pragma unroll
        for (int it = 0; it < 7; it++) {
            int flat = it*256 + tid;
            if (flat < 1600) {
                int pos = flat >> 3, c4 = flat & 7;
                int hr = pos / 20, hc = pos % 20;
                int gr = r0 + hr, gc = c0 - 6 + hc;
                float4 v = make_float4(0.f, 0.f, 0.f, 0.f);
                if (gr < 54 && gc >= 0 && gc < 54)
                    v = *(const float4*)&g_QK[(long)((b*NPOS + gr*54 + gc))*256 + cc + c4*4];
                sQ4[pos*9 + c4] = v;
            }
        }
        __syncthreads();
        #pragma unroll
        for (int c4 = 0; c4 < 8; c4++) {
            float4 q = sQ4[own4 + c4];
            #pragma unroll
            for (int k = 0; k < 11; k++) {
                float4 v = sQ4[own4 + doff[k] + c4];
                acc[k] += q.x*v.x + q.y*v.y + q.z*v.z + q.w*v.w;
            }
        }
        __syncthreads();
    }
    int gr = r0 + pr, gc = c0 + pc;
    if (gr < 54 && gc < 54) {
        int pg = b*NPOS + gr*54 + gc;
        #pragma unroll
        for (int k = 0; k < 11; k++) {
            int t = dbase + k;
            if (t < 85) g_CORR[t*NP2 + pg] = acc[k];
        }
    }
}

// ---------------------------------------------------------------------------
// Kernel 3: bias projections, warp-per-position, float4 coalesced.
__global__ void __launch_bounds__(256) kAB(const float* __restrict__ relh,
                                           const float* __restrict__ relw) {
    __shared__ float sR[2][7][128];
    int tid = threadIdx.x;
    for (int i = tid; i < 1792; i += 256) {
        int half = i / 896, j = i % 896;
        int r = j / 128, o = j % 128;
        sR[half][r][o] = (half == 0) ? relh[o*7 + r] : relw[o*7 + r];
    }
    __syncthreads();

    int lane = tid & 31, wid = tid >> 5;
    int p = blockIdx.x * 8 + wid;
    const float* qrow = &g_QK[(long)p*256];
    float4 q1 = *(const float4*)&qrow[4*lane];
    float4 q2 = *(const float4*)&qrow[128 + 4*lane];

    #pragma unroll
    for (int r = 0; r < 7; r++) {
        float4 rh = *(const float4*)&sR[0][r][4*lane];
        float4 rw = *(const float4*)&sR[1][r][4*lane];
        float sh = rh.x*q1.x + rh.y*q1.y + rh.z*q1.z + rh.w*q1.w;
        float sw = rw.x*q2.x + rw.y*q2.y + rw.z*q2.z + rw.w*q2.w;
        #pragma unroll
        for (int o = 16; o; o >>= 1) {
            sh += __shfl_xor_sync(0xffffffffu, sh, o);
            sw += __shfl_xor_sync(0xffffffffu, sw, o);
        }
        if (lane == 0) {
            g_AB[(long)p*16 + r]     = sh;
            g_AB[(long)p*16 + 8 + r] = sw;
        }
    }
}

// ---------------------------------------------------------------------------
// Kernel 4: 8-px row strip. DOUBLE-BUFFERED cp.async B1 (L2 wait hidden behind
// B2 of previous chunk); softmax reductions via __reduce_{max,add}_sync
// (order-preserving int trick for max, 2^21 fixed point for the exp sum).
// Layout (float units):
//   S_ABT = 0    : 16 x 98  bias projections [e][r*14+c]     (6.3 KB)
//   S_S0  = 1568 : 343 x 9  corr chunk buf 0                 (12.3 KB)
//   S_S1  = 4655 : 343 x 9  corr chunk buf 1                 (12.3 KB)
//   S_WV  = 7742 : 49 x 9   avg weights                      (1.8 KB)
//   Phase C: sV (98 x 68 = 6664 floats) overlays [0..6664) — sWv survives.
#define S_ABT 0
#define S_S0  1568
#define S_S1  4655
#define S_WV  7742
#define SMEM_FLOATS 8183    // 32732 bytes (static)

__device__ __forceinline__ void issue_chunk(const float* pC, float* sSb,
                                            int ebase, int qid, int pxc) {
    #pragma unroll
    for (int it = 0; it < 10; it++) {
        int q = it*32 + qid;
        unsigned int t = c_tab.v[ebase + q];
        cpa4((unsigned int)__cvta_generic_to_shared(&sSb[q*9 + pxc]), pC + t);
    }
    if (qid < 23) {
        int q = 320 + qid;
        unsigned int t = c_tab.v[ebase + q];
        cpa4((unsigned int)__cvta_generic_to_shared(&sSb[q*9 + pxc]), pC + t);
    }
    asm volatile("cp.async.commit_group;" ::: "memory");
}

__global__ void __launch_bounds__(256) kAttn(float* __restrict__ out) {
    __shared__ __align__(16) float smem[SMEM_FLOATS];
    float* sABt = smem + S_ABT;
    float* sS0  = smem + S_S0;
    float* sS1  = smem + S_S1;
    float* sWv  = smem + S_WV;
    float* sV   = smem;              // phase-C overlay

    int tid = threadIdx.x;
    int w0 = blockIdx.x * 8;
    int h  = blockIdx.y;
    int b  = blockIdx.z;
    int bbase = b*NPOS;
    int blkbase = bbase + h*54 + w0;

    int pxc = tid & 7, qid = tid >> 3;        // B1 mapping
    const float* pC = g_CORR + blkbase + pxc;

    // Kick off chunks 0 and 1 immediately (independent of sABt staging)
    issue_chunk(pC, sS0, 0,   qid, pxc);
    issue_chunk(pC, sS1, 343, qid, pxc);

    // Stage bias projections [e][pos], stride 98 (1568 = 6*256 + 32)
    #pragma unroll
    for (int it = 0; it < 7; it++) {
        int i = it*256 + tid;
        if (i < 1568) {
            int e = i & 15, p2 = i >> 4;
            int r = p2 / 14, cpos = p2 % 14;
            sABt[e*98 + p2] = g_AB[(long)(bbase + (h+r)*54 + w0 + cpos)*16 + e];
        }
    }

    float wacc0 = 0.f, wacc1 = 0.f;
    int lane = tid & 31, px_b = tid >> 5;     // B2: warp px_b, lane = column
    int l32 = lane + 32;
    bool has1 = lane < 17;
    int jm0 = (lane/7)*14 + lane%7;
    int jm1 = (l32/7)*14 + l32%7;

    for (int chk = 0; chk < 7; chk++) {
        if (chk < 6) asm volatile("cp.async.wait_group 1;" ::: "memory");
        else         asm volatile("cp.async.wait_group 0;" ::: "memory");
        __syncthreads();
        float* sSc = (chk & 1) ? sS1 : sS0;
        // B2: bias add + softmax via warp redux; accumulate column sums
        float a0 = sABt[chk*98 + jm0 + px_b];
        float a1 = has1 ? sABt[chk*98 + jm1 + px_b] : 0.f;
        #pragma unroll
        for (int rr = 0; rr < 7; rr++) {
            const float* pBr = sABt + (8+rr)*98 + px_b;
            float v0 = sSc[(rr*49 + lane)*9 + px_b] + a0 + pBr[jm0];
            float v1 = has1 ? (sSc[(rr*49 + l32)*9 + px_b] + a1 + pBr[jm1]) : -1e30f;
            // warp max via order-preserving int map + u32 redux
            float v01 = fmaxf(v0, v1);
            int sb = __float_as_int(v01);
            unsigned int u = (unsigned int)(sb ^ ((sb >> 31) | 0x80000000));
            unsigned int um = __reduce_max_sync(0xffffffffu, u);
            int mb = (um & 0x80000000u) ? (int)(um ^ 0x80000000u) : ~(int)um;
            float m = __int_as_float(mb);
            float e0 = __expf(v0 - m);
            float e1 = has1 ? __expf(v1 - m) : 0.f;
            // warp sum via 2^21 fixed point redux (e in [0,1], 49 terms)
            unsigned int qfx = __float2uint_rn((e0 + e1) * 2097152.0f);
            unsigned int qs = __reduce_add_sync(0xffffffffu, qfx);
            float inv = 2097152.0f / (float)qs;
            wacc0 += e0*inv; wacc1 += e1*inv;
        }
        __syncthreads();
        if (chk < 5) issue_chunk(pC, sSc, (chk+2)*343, qid, pxc);
    }
    sWv[lane*9 + px_b] = wacc0 * (1.f/49.f);
    if (has1) sWv[l32*9 + px_b] = wacc1 * (1.f/49.f);
    __syncthreads();

    // Phase C: V gather via smem staging, 64-channel chunks, float2/thread
    int px = tid & 7, tc = tid >> 3;        // tc in [0,32): channel pair
    for (int cc = 0; cc < 256; cc += 64) {
        #pragma unroll
        for (int it = 0; it < 7; it++) {
            int i = it*256 + tid;
            if (i < 1568) {
                int f4 = i & 15, p2 = i >> 4;
                int r = p2 / 14, cpos = p2 % 14;
                *(float4*)&sV[p2*68 + f4*4] =
                    *(const float4*)&g_V[(long)(bbase + (h+r)*54 + w0 + cpos)*256 + cc + f4*4];
            }
        }
        __syncthreads();
        float2 acc = make_float2(0.f, 0.f);
        #pragma unroll
        for (int jj = 0; jj < 49; jj++) {
            int jpos = (jj/7)*14 + (jj%7);
            float w = sWv[jj*9 + px];
            float2 v = *(const float2*)&sV[(jpos + px)*68 + tc*2];
            acc.x += w*v.x; acc.y += w*v.y;
        }
        int c = cc + tc*2;
        int ob = ((b*256 + c)*48 + h)*48 + w0 + px;
        out[ob]        = acc.x;
        out[ob + 2304] = acc.y;
        __syncthreads();
    }
}

// ---------------------------------------------------------------------------
extern "C" void kernel_launch(void* const* d_in, const int* in_sizes, int n_in,
                              void* d_out, int out_size) {
    const float* x    = (const float*)d_in[0];
    const float* wk   = (const float*)d_in[1];
    const float* wv   = (const float*)d_in[2];
    const float* relh = (const float*)d_in[3];
    const float* relw = (const float*)d_in[4];
    float* out = (float*)d_out;

    kGemmZ<<<dim3(36, 5), 256>>>(x, wk, wv);
    kCorr<<<dim3(7, 14, 2), 256>>>();
    kAB<<<729, 256>>>(relh, relw);
    kAttn<<<dim3(6, 48, 2), 256>>>(out);
}

// round 14
// speedup vs baseline: 1.0564x; 1.0376x over previous
#include <cuda_runtime.h>

#define BB 2
#define CIN 256
#define OCH 256
#define HH 48
#define WW 48
#define HP 54
#define WP 54
#define NPOS (HP*WP)      // 2916
#define NP2 (BB*NPOS)     // 5832
#define KS 7
#define KK 49
#define ND2 85            // symmetric offsets: dr=0,dc>=0 (7) + dr in [1,6] x dc in [-6,6] (78)

// Scratch (device globals: no allocation allowed)
__device__ float g_QK[BB*NPOS*OCH];      // [b][p][o]   ~6.0 MB
__device__ float g_V [BB*NPOS*OCH];      // [b][p][o]   ~6.0 MB
__device__ float g_CORR[ND2*NP2];        // [d][b*NPOS+p]  ~2.0 MB  (offset-major)
__device__ float g_AB[BB*NPOS*16];       // [b][p][0..6]=A(rel_h), [8..14]=B(rel_w)

// Compile-time (block-independent) corr-offset table: di*NP2 + r*54 + c.
// Lives in GLOBAL memory (not __constant__): per-warp indices span 4 consecutive
// words -> one 16B sector via LDG (L1-resident), no constant-cache replays.
struct CorrTab { unsigned int v[2401]; };
static constexpr CorrTab make_tab() {
    CorrTab t{};
    for (int e = 0; e < 2401; e++) {
        int ii = e / 49, jj = e % 49;
        int ir = ii / 7, ic = ii % 7, jr = jj / 7, jc = jj % 7;
        int dr = jr - ir, dc = jc - ic;
        int r = 0, c = 0;
        if (dr > 0 || (dr == 0 && dc >= 0)) { r = ir; c = ic; }
        else { r = jr; c = jc; dr = -dr; dc = -dc; }
        int di = (dr == 0) ? dc : (7 + (dr - 1)*13 + dc + 6);
        t.v[e] = (unsigned int)(di*NP2 + r*54 + c);
    }
    return t;
}
__device__ CorrTab g_tab = make_tab();

// packed f32x2 FMA (Blackwell)
__device__ __forceinline__ void ffma2(unsigned long long &d, unsigned long long a, unsigned long long b) {
    asm("fma.rn.f32x2 %0, %1, %2, %0;" : "+l"(d) : "l"(a), "l"(b));
}
__device__ __forceinline__ float2 u2f(unsigned long long u) {
    float2 f; asm("mov.b64 {%0,%1}, %2;" : "=f"(f.x), "=f"(f.y) : "l"(u)); return f;
}
__device__ __forceinline__ unsigned long long dup2(float a) {
    unsigned long long r; asm("mov.b64 %0, {%1, %1};" : "=l"(r) : "f"(a)); return r;
}
// 4-byte async copy global->shared (LDGSTS): no result register, high MLP.
__device__ __forceinline__ void cpa4(unsigned int saddr, const float* g) {
    asm volatile("cp.async.ca.shared.global [%0], [%1], 4;" :: "r"(saddr), "l"(g));
}

// ---------------------------------------------------------------------------
// Kernel 1: fused {border-zero + 1x1 conv GEMM}.
__global__ void __launch_bounds__(256) kGemmZ(const float* __restrict__ x,
                                              const float* __restrict__ wk,
                                              const float* __restrict__ wv) {
    if (blockIdx.y == 4) {       // border zeroing
        float4 z = make_float4(0.f, 0.f, 0.f, 0.f);
        for (int idx = blockIdx.x*256 + threadIdx.x; idx < 156672; idx += 9216) {
            int c4  = idx & 63;
            int t   = idx >> 6;
            int bp  = t % 612;
            int t2  = t / 612;
            int b   = t2 & 1;
            int arr = t2 >> 1;
            int row, col;
            if (bp < 324) { int r = bp / 54; row = (r < 3) ? r : r + 48; col = bp % 54; }
            else { int u = bp - 324; row = 3 + u / 6; int c6 = u % 6; col = (c6 < 3) ? c6 : c6 + 48; }
            long off = ((long)(b*NPOS + row*54 + col)*256) + c4*4;
            if (arr == 0) *(float4*)&g_QK[off] = z;
            else          *(float4*)&g_V [off] = z;
        }
        return;
    }
    __shared__ float As[16][132];
    __shared__ float Bs[16][132];
    int tid = threadIdx.x;
    int n0 = blockIdx.x * 128;
    int m0 = blockIdx.y * 128;
    int tx = tid & 15, ty = tid >> 4;
    unsigned long long acc[8][4];
    #pragma unroll
    for (int i = 0; i < 8; i++)
        #pragma unroll
        for (int j = 0; j < 4; j++) acc[i][j] = 0ull;

    for (int kt = 0; kt < 256; kt += 16) {
        #pragma unroll
        for (int i = 0; i < 8; i++) {
            int flat = i*256 + tid;
            int k = flat >> 7, n = flat & 127;
            int nn = n0 + n;
            int b = nn / 2304, s = nn % 2304;
            As[k][n] = x[(b*256 + kt + k)*2304 + s];
        }
        #pragma unroll
        for (int i = 0; i < 8; i++) {
            int flat = i*256 + tid;
            int k = flat & 15, m = flat >> 4;
            int mm = m0 + m;
            Bs[k][m] = (mm < 256) ? wk[mm*256 + kt + k] : wv[(mm-256)*256 + kt + k];
        }
        __syncthreads();
        #pragma unroll
        for (int k = 0; k < 16; k++) {
            float4 a03 = *(const float4*)&As[k][4*ty];
            float4 a47 = *(const float4*)&As[k][64 + 4*ty];
            ulonglong2 b03 = *(const ulonglong2*)&Bs[k][4*tx];
            ulonglong2 b47 = *(const ulonglong2*)&Bs[k][64 + 4*tx];
            unsigned long long A[8] = {dup2(a03.x), dup2(a03.y), dup2(a03.z), dup2(a03.w),
                                       dup2(a47.x), dup2(a47.y), dup2(a47.z), dup2(a47.w)};
            unsigned long long B[4] = {b03.x, b03.y, b47.x, b47.y};
            #pragma unroll
            for (int i = 0; i < 8; i++)
                #pragma unroll
                for (int j = 0; j < 4; j++)
                    ffma2(acc[i][j], A[i], B[j]);
        }
        __syncthreads();
    }
    #pragma unroll
    for (int i = 0; i < 8; i++) {
        int n = n0 + ((i < 4) ? (ty*4 + i) : (64 + ty*4 + i - 4));
        int b = n / 2304, rem = n % 2304;
        int h = rem / 48, w = rem % 48;
        int pidx = (h + 3)*54 + (w + 3);
        long rowq = (long)(b*NPOS + pidx)*256;
        float2 p0 = u2f(acc[i][0]), p1 = u2f(acc[i][1]);
        float2 p2 = u2f(acc[i][2]), p3 = u2f(acc[i][3]);
        float4 va = make_float4(p0.x, p0.y, p1.x, p1.y);
        float4 vb = make_float4(p2.x, p2.y, p3.x, p3.y);
        int ma = m0 + tx*4;
        int mb = m0 + 64 + tx*4;
        if (ma < 256) *(float4*)&g_QK[rowq + ma]        = va;
        else          *(float4*)&g_V [rowq + (ma-256)]  = va;
        if (mb < 256) *(float4*)&g_QK[rowq + mb]        = vb;
        else          *(float4*)&g_V [rowq + (mb-256)]  = vb;
    }
}

// ---------------------------------------------------------------------------
// Kernel 2: fused CORR + bias projections.
// CORR[d][b,p] = sum_c QK[b,p,c]*QK[b,p+d,c] for 85 symmetric offsets.
// AB[p][r]   = sum_{o<128}  relh[o,r]*QK[p][o]        (warp wg accumulates r=wg)
// AB[p][8+r] = sum_{o<128}  relw[o,r]*QK[p][128+o]
__global__ void kCorrAB(const float* __restrict__ relh,
                        const float* __restrict__ relw) {
    __shared__ float4 sQ4[10*20*9];
    __shared__ float sRh[7][128];
    __shared__ float sRw[7][128];
    int b  = blockIdx.z;
    int r0 = blockIdx.y * 4;
    int c0 = blockIdx.x * 8;
    int tid = threadIdx.x;
    int pl = tid & 31;
    int wg = tid >> 5;
    int pr = pl >> 3, pc = pl & 7;
    int dbase = wg * 11;

    // Stage rel weights transposed: sRh[r][o] = relh[o*7+r]
    for (int i = tid; i < 1792; i += 256) {
        int half = i / 896, j = i % 896;
        int r = j % 7, o = j / 7;
        if (half == 0) sRh[r][o] = relh[j];
        else           sRw[r][o] = relw[j];
    }

    int doff[11];
    #pragma unroll
    for (int k = 0; k < 11; k++) {
        int t = dbase + k; if (t > 84) t = 84;
        int dr, dc;
        if (t < 7) { dr = 0; dc = t; }
        else { int u = t - 7; dr = u/13 + 1; dc = u%13 - 6; }
        doff[k] = (dr*20 + dc) * 9;
    }
    float acc[11];
    #pragma unroll
    for (int k = 0; k < 11; k++) acc[k] = 0.f;
    float accA = 0.f, accB = 0.f;

    int own4 = (pr*20 + (pc + 6)) * 9;
    bool doAB = (wg < 7);

    for (int cc = 0; cc < 256; cc += 32) {
        #pragma unroll
        for (int it = 0; it < 7; it++) {
            int flat = it*256 + tid;
            if (flat < 1600) {
                int pos = flat >> 3, c4 = flat & 7;
                int hr = pos / 20, hc = pos % 20;
                int gr = r0 + hr, gc = c0 - 6 + hc;
                float4 v = make_float4(0.f, 0.f, 0.f, 0.f);
                if (gr < 54 && gc >= 0 && gc < 54)
                    v = *(const float4*)&g_QK[(long)((b*NPOS + gr*54 + gc))*256 + cc + c4*4];
                sQ4[pos*9 + c4] = v;
            }
        }
        __syncthreads();
        const float* rbase = (cc < 128) ? &sRh[doAB ? wg : 0][cc]
                                        : &sRw[doAB ? wg : 0][cc - 128];
        float accR = 0.f;
        #pragma unroll
        for (int c4 = 0; c4 < 8; c4++) {
            float4 q = sQ4[own4 + c4];
            #pragma unroll
            for (int k = 0; k < 11; k++) {
                float4 v = sQ4[own4 + doff[k] + c4];
                acc[k] += q.x*v.x + q.y*v.y + q.z*v.z + q.w*v.w;
            }
            float4 rv = *(const float4*)&rbase[c4*4];   // warp-uniform broadcast
            accR += q.x*rv.x + q.y*rv.y + q.z*rv.z + q.w*rv.w;
        }
        if (cc < 128) accA += accR; else accB += accR;
        __syncthreads();
    }
    int gr = r0 + pr, gc = c0 + pc;
    if (gr < 54 && gc < 54) {
        int pg = b*NPOS + gr*54 + gc;
        #pragma unroll
        for (int k = 0; k < 11; k++) {
            int t = dbase + k;
            if (t < 85) g_CORR[t*NP2 + pg] = acc[k];
        }
        if (doAB) {
            g_AB[(long)pg*16 + wg]     = accA;
            g_AB[(long)pg*16 + 8 + wg] = accB;
        }
    }
}

// ---------------------------------------------------------------------------
// Kernel 3: 8-px row strip. Double-buffered cp.async B1 (offset table via LDG,
// L1-resident); softmax via __reduce_{max,add}_sync.
// Layout (float units):
//   S_ABT = 0    : 16 x 98  bias projections [e][r*14+c]     (6.3 KB)
//   S_S0  = 1568 : 343 x 9  corr chunk buf 0                 (12.3 KB)
//   S_S1  = 4655 : 343 x 9  corr chunk buf 1                 (12.3 KB)
//   S_WV  = 7742 : 49 x 9   avg weights                      (1.8 KB)
//   Phase C: sV (98 x 68 = 6664 floats) overlays [0..6664) — sWv survives.
#define S_ABT 0
#define S_S0  1568
#define S_S1  4655
#define S_WV  7742
#define SMEM_FLOATS 8183    // 32732 bytes (static)

__device__ __forceinline__ void issue_chunk(const float* pC, float* sSb,
                                            int ebase, int qid, int pxc) {
    #pragma unroll
    for (int it = 0; it < 10; it++) {
        int q = it*32 + qid;
        unsigned int t = g_tab.v[ebase + q];
        cpa4((unsigned int)__cvta_generic_to_shared(&sSb[q*9 + pxc]), pC + t);
    }
    if (qid < 23) {
        int q = 320 + qid;
        unsigned int t = g_tab.v[ebase + q];
        cpa4((unsigned int)__cvta_generic_to_shared(&sSb[q*9 + pxc]), pC + t);
    }
    asm volatile("cp.async.commit_group;" ::: "memory");
}

__global__ void __launch_bounds__(256) kAttn(float* __restrict__ out) {
    __shared__ __align__(16) float smem[SMEM_FLOATS];
    float* sABt = smem + S_ABT;
    float* sS0  = smem + S_S0;
    float* sS1  = smem + S_S1;
    float* sWv  = smem + S_WV;
    float* sV   = smem;              // phase-C overlay

    int tid = threadIdx.x;
    int w0 = blockIdx.x * 8;
    int h  = blockIdx.y;
    int b  = blockIdx.z;
    int bbase = b*NPOS;
    int blkbase = bbase + h*54 + w0;

    int pxc = tid & 7, qid = tid >> 3;        // B1 mapping
    const float* pC = g_CORR + blkbase + pxc;

    // Kick off chunks 0 and 1 immediately (independent of sABt staging)
    issue_chunk(pC, sS0, 0,   qid, pxc);
    issue_chunk(pC, sS1, 343, qid, pxc);

    // Stage bias projections [e][pos], stride 98 (1568 = 6*256 + 32)
    #pragma unroll
    for (int it = 0; it < 7; it++) {
        int i = it*256 + tid;
        if (i < 1568) {
            int e = i & 15, p2 = i >> 4;
            int r = p2 / 14, cpos = p2 % 14;
            sABt[e*98 + p2] = g_AB[(long)(bbase + (h+r)*54 + w0 + cpos)*16 + e];
        }
    }

    float wacc0 = 0.f, wacc1 = 0.f;
    int lane = tid & 31, px_b = tid >> 5;     // B2: warp px_b, lane = column
    int l32 = lane + 32;
    bool has1 = lane < 17;
    int jm0 = (lane/7)*14 + lane%7;
    int jm1 = (l32/7)*14 + l32%7;

    for (int chk = 0; chk < 7; chk++) {
        if (chk < 6) asm volatile("cp.async.wait_group 1;" ::: "memory");
        else         asm volatile("cp.async.wait_group 0;" ::: "memory");
        __syncthreads();
        float* sSc = (chk & 1) ? sS1 : sS0;
        // B2: bias add + softmax via warp redux; accumulate column sums
        float a0 = sABt[chk*98 + jm0 + px_b];
        float a1 = has1 ? sABt[chk*98 + jm1 + px_b] : 0.f;
        #pragma unroll
        for (int rr = 0; rr < 7; rr++) {
            const float* pBr = sABt + (8+rr)*98 + px_b;
            float v0 = sSc[(rr*49 + lane)*9 + px_b] + a0 + pBr[jm0];
            float v1 = has1 ? (sSc[(rr*49 + l32)*9 + px_b] + a1 + pBr[jm1]) : -1e30f;
            // warp max via order-preserving int map + u32 redux
            float v01 = fmaxf(v0, v1);
            int sb = __float_as_int(v01);
            unsigned int u = (unsigned int)(sb ^ ((sb >> 31) | 0x80000000));
            unsigned int um = __reduce_max_sync(0xffffffffu, u);
            int mb = (um & 0x80000000u) ? (int)(um ^ 0x80000000u) : ~(int)um;
            float m = __int_as_float(mb);
            float e0 = __expf(v0 - m);
            float e1 = has1 ? __expf(v1 - m) : 0.f;
            // warp sum via 2^21 fixed point redux (e in [0,1], 49 terms)
            unsigned int qfx = __float2uint_rn((e0 + e1) * 2097152.0f);
            unsigned int qs = __reduce_add_sync(0xffffffffu, qfx);
            float inv = 2097152.0f / (float)qs;
            wacc0 += e0*inv; wacc1 += e1*inv;
        }
        __syncthreads();
        if (chk < 5) issue_chunk(pC, sSc, (chk+2)*343, qid, pxc);
    }
    sWv[lane*9 + px_b] = wacc0 * (1.f/49.f);
    if (has1) sWv[l32*9 + px_b] = wacc1 * (1.f/49.f);
    __syncthreads();

    // Phase C: V gather via smem staging, 64-channel chunks, float2/thread
    int px = tid & 7, tc = tid >> 3;        // tc in [0,32): channel pair
    for (int cc = 0; cc < 256; cc += 64) {
        #pragma unroll
        for (int it = 0; it < 7; it++) {
            int i = it*256 + tid;
            if (i < 1568) {
                int f4 = i & 15, p2 = i >> 4;
                int r = p2 / 14, cpos = p2 % 14;
                *(float4*)&sV[p2*68 + f4*4] =
                    *(const float4*)&g_V[(long)(bbase + (h+r)*54 + w0 + cpos)*256 + cc + f4*4];
            }
        }
        __syncthreads();
        float2 acc = make_float2(0.f, 0.f);
        #pragma unroll
        for (int jj = 0; jj < 49; jj++) {
            int jpos = (jj/7)*14 + (jj%7);
            float w = sWv[jj*9 + px];
            float2 v = *(const float2*)&sV[(jpos + px)*68 + tc*2];
            acc.x += w*v.x; acc.y += w*v.y;
        }
        int c = cc + tc*2;
        int ob = ((b*256 + c)*48 + h)*48 + w0 + px;
        out[ob]        = acc.x;
        out[ob + 2304] = acc.y;
        __syncthreads();
    }
}

// ---------------------------------------------------------------------------
extern "C" void kernel_launch(void* const* d_in, const int* in_sizes, int n_in,
                              void* d_out, int out_size) {
    const float* x    = (const float*)d_in[0];
    const float* wk   = (const float*)d_in[1];
    const float* wv   = (const float*)d_in[2];
    const float* relh = (const float*)d_in[3];
    const float* relw = (const float*)d_in[4];
    float* out = (float*)d_out;

    kGemmZ<<<dim3(36, 5), 256>>>(x, wk, wv);
    kCorrAB<<<dim3(7, 14, 2), 256>>>(relh, relw);
    kAttn<<<dim3(6, 48, 2), 256>>>(out);
}